// round 3
// baseline (speedup 1.0000x reference)
#include <cuda_runtime.h>
#include <math_constants.h>

#define SIZE 28
#define TSTEPS 64
#define PITCH 32        // floats per t-row in shared (bank/float4 friendly)
#define NTHREADS 224    // 7 warps; 196 active in mainloop; 1792/224 = 8 prologue iters

__global__ __launch_bounds__(NTHREADS) void draw_image_kernel(
    const float* __restrict__ x,   // (B, T, 3)
    float* __restrict__ out)       // (B, SIZE, SIZE)
{
    __shared__ float s_px [TSTEPS * PITCH];  // log-domain: -g*(rng[c]-x_t)^2
    __shared__ float s_pyw[TSTEPS * PITCH];  // log-domain: log(si_t) - g*(rng[r]-y_t)^2
    __shared__ float s_x  [TSTEPS * 3];      // staged stroke params (192 floats)
    __shared__ float s_ls [TSTEPS];          // log(si_t)

    const int b = blockIdx.x;
    const int tid = threadIdx.x;
    const float* xb = x + (size_t)b * TSTEPS * 3;

    const float g = (SIZE * 0.5f) * (SIZE * 0.5f);  // 196
    const float inv_size = 1.0f / SIZE;

    // Phase 0: coalesced stage of stroke params (192 floats = 48 float4).
    if (tid < 48) ((float4*)s_x)[tid] = ((const float4*)xb)[tid];
    __syncthreads();

    // Phase 1: one log per stroke (64 MUFU.LG2 total).
    if (tid < TSTEPS) s_ls[tid] = __logf(s_x[3 * tid + 2]);
    __syncthreads();

    // Phase 2: log-domain tables — pure FMA math, no exp.
    #pragma unroll
    for (int it = 0; it < 8; it++) {
        const int i = tid + it * NTHREADS;
        const int t = i / SIZE;
        const int c = i - t * SIZE;
        const float rng = (float)c * inv_size - 0.5f;

        const float sx = s_x[3 * t + 0];
        const float sy = s_x[3 * t + 1];

        const float dx = rng - sx;
        s_px[t * PITCH + c] = (dx * dx) * (-g);

        const float dy = rng - sy;
        s_pyw[t * PITCH + c] = fmaf(dy * dy, -g, s_ls[t]);
    }
    __syncthreads();

    // Mainloop: 196 units = (colgroup cg in [0,7)) x (row r in [0,28)).
    // float4 px load is a 2-address broadcast per warp; pyw load is
    // bank-spread/broadcast — both conflict-free.
    if (tid < 196) {
        const int cg = tid / SIZE;        // 0..6
        const int r  = tid - cg * SIZE;   // 0..27

        const float4* px4 = (const float4*)s_px;  // [t * (PITCH/4) + cg]

        const float ninf = -CUDART_INF_F;
        float a0 = ninf, a1 = ninf, a2 = ninf, a3 = ninf;
        #pragma unroll
        for (int t = 0; t < TSTEPS; t++) {
            const float w  = s_pyw[t * PITCH + r];
            const float4 p = px4[t * (PITCH / 4) + cg];
            a0 = fmaxf(a0, w + p.x);
            a1 = fmaxf(a1, w + p.y);
            a2 = fmaxf(a2, w + p.z);
            a3 = fmaxf(a3, w + p.w);
        }

        // Leave log domain: 4 exps per thread (784 per CTA).
        float* outp = out + (size_t)b * SIZE * SIZE + r * SIZE + cg * 4;
        *(float4*)outp = make_float4(__expf(a0), __expf(a1), __expf(a2), __expf(a3));
    }
}

extern "C" void kernel_launch(void* const* d_in, const int* in_sizes, int n_in,
                              void* d_out, int out_size)
{
    const float* x = (const float*)d_in[0];
    float* out = (float*)d_out;

    const int B = in_sizes[0] / (TSTEPS * 3);  // 1024

    draw_image_kernel<<<B, NTHREADS>>>(x, out);
}